// round 1
// baseline (speedup 1.0000x reference)
#include <cuda_runtime.h>

// GCN layer:
//   h   = feat / out_norm[:,None]
//   agg = segment_sum(h[edge_src], edge_dst)
//   x   = agg / in_norm[:,None]
//   out = x @ W.T + b
//
// inputs (metadata order): feat[100000,64] f32, in_norm[100000] f32,
//   out_norm[100000] f32, edge_src[1600000] i32, edge_dst[1600000] i32,
//   W[64,64] f32, b[64] f32
// output: [100000,64] f32

#define N_NODES 100000
#define N_EDGES 1600000
#define D 64

// Scratch accumulator (25.6 MB) — static device array per harness rules.
__device__ float g_agg[N_NODES * D];

// ---------------------------------------------------------------------------
// Kernel 1: zero the accumulator (float4 stores)
// ---------------------------------------------------------------------------
__global__ void zero_agg_kernel() {
    int t = blockIdx.x * blockDim.x + threadIdx.x;
    if (t < N_NODES * D / 4) {
        reinterpret_cast<float4*>(g_agg)[t] = make_float4(0.f, 0.f, 0.f, 0.f);
    }
}

// ---------------------------------------------------------------------------
// Kernel 2: edge gather + scatter-add.
// One thread per (edge, 4-float chunk): 16 threads/edge.
// feat row and agg row are 256B each; both arrays are L2-resident (25.6 MB).
// Uses red.global.add.v4.f32 (sm_90+) -> 1 vector reduction per 16 bytes.
// ---------------------------------------------------------------------------
__global__ __launch_bounds__(256) void edge_scatter_kernel(
    const float* __restrict__ feat,
    const float* __restrict__ out_norm,
    const int*   __restrict__ edge_src,
    const int*   __restrict__ edge_dst)
{
    int t = blockIdx.x * blockDim.x + threadIdx.x;   // 0 .. N_EDGES*16
    int e = t >> 4;
    int c = t & 15;
    if (e >= N_EDGES) return;

    int s = __ldg(edge_src + e);
    int d = __ldg(edge_dst + e);
    float inv = __fdividef(1.0f, __ldg(out_norm + s));

    float4 f = __ldg(reinterpret_cast<const float4*>(feat) + s * (D / 4) + c);

    float* a = g_agg + d * D + c * 4;
    asm volatile("red.global.add.v4.f32 [%0], {%1, %2, %3, %4};"
                 :: "l"(a), "f"(f.x * inv), "f"(f.y * inv),
                    "f"(f.z * inv), "f"(f.w * inv)
                 : "memory");
}

// ---------------------------------------------------------------------------
// Kernel 3: x = agg / in_norm; out = x @ W.T + b.
// One thread per node. x row (64 f32) lives in registers; W (16 KB) staged in
// shared memory; W reads are warp-uniform -> LDS broadcast (conflict-free).
// ---------------------------------------------------------------------------
__global__ __launch_bounds__(256) void out_linear_kernel(
    const float* __restrict__ in_norm,
    const float* __restrict__ W,      // [D_OUT, D_IN] row-major
    const float* __restrict__ b,
    float*       __restrict__ out)
{
    __shared__ float Ws[D * D];
    __shared__ float bs[D];

    for (int i = threadIdx.x; i < D * D / 4; i += blockDim.x) {
        reinterpret_cast<float4*>(Ws)[i] = __ldg(reinterpret_cast<const float4*>(W) + i);
    }
    if (threadIdx.x < D) bs[threadIdx.x] = __ldg(b + threadIdx.x);
    __syncthreads();

    int n = blockIdx.x * blockDim.x + threadIdx.x;
    if (n >= N_NODES) return;

    float inv = __fdividef(1.0f, __ldg(in_norm + n));

    float x[D];
    const float4* ar = reinterpret_cast<const float4*>(g_agg + n * D);
    #pragma unroll
    for (int i = 0; i < D / 4; i++) {
        float4 v = ar[i];
        x[4 * i + 0] = v.x * inv;
        x[4 * i + 1] = v.y * inv;
        x[4 * i + 2] = v.z * inv;
        x[4 * i + 3] = v.w * inv;
    }

    float4* orow = reinterpret_cast<float4*>(out + n * D);
    #pragma unroll 2
    for (int o4 = 0; o4 < D / 4; o4++) {
        float a0 = bs[4 * o4 + 0];
        float a1 = bs[4 * o4 + 1];
        float a2 = bs[4 * o4 + 2];
        float a3 = bs[4 * o4 + 3];
        const float4* w0 = reinterpret_cast<const float4*>(Ws + (4 * o4 + 0) * D);
        const float4* w1 = reinterpret_cast<const float4*>(Ws + (4 * o4 + 1) * D);
        const float4* w2 = reinterpret_cast<const float4*>(Ws + (4 * o4 + 2) * D);
        const float4* w3 = reinterpret_cast<const float4*>(Ws + (4 * o4 + 3) * D);
        #pragma unroll
        for (int i = 0; i < D / 4; i++) {
            float4 v0 = w0[i];
            float4 v1 = w1[i];
            float4 v2 = w2[i];
            float4 v3 = w3[i];
            float x0 = x[4 * i + 0], x1 = x[4 * i + 1];
            float x2 = x[4 * i + 2], x3 = x[4 * i + 3];
            a0 += x0 * v0.x + x1 * v0.y + x2 * v0.z + x3 * v0.w;
            a1 += x0 * v1.x + x1 * v1.y + x2 * v1.z + x3 * v1.w;
            a2 += x0 * v2.x + x1 * v2.y + x2 * v2.z + x3 * v2.w;
            a3 += x0 * v3.x + x1 * v3.y + x2 * v3.z + x3 * v3.w;
        }
        orow[o4] = make_float4(a0, a1, a2, a3);
    }
}

// ---------------------------------------------------------------------------
extern "C" void kernel_launch(void* const* d_in, const int* in_sizes, int n_in,
                              void* d_out, int out_size)
{
    const float* feat     = (const float*)d_in[0];
    const float* in_norm  = (const float*)d_in[1];
    const float* out_norm = (const float*)d_in[2];
    const int*   edge_src = (const int*)  d_in[3];
    const int*   edge_dst = (const int*)  d_in[4];
    const float* W        = (const float*)d_in[5];
    const float* b        = (const float*)d_in[6];
    float*       out      = (float*)d_out;

    (void)in_sizes; (void)n_in; (void)out_size;

    {
        int n = N_NODES * D / 4;
        zero_agg_kernel<<<(n + 255) / 256, 256>>>();
    }
    {
        long total = (long)N_EDGES * 16;
        int blocks = (int)((total + 255) / 256);
        edge_scatter_kernel<<<blocks, 256>>>(feat, out_norm, edge_src, edge_dst);
    }
    {
        out_linear_kernel<<<(N_NODES + 255) / 256, 256>>>(in_norm, W, b, out);
    }
}